// round 7
// baseline (speedup 1.0000x reference)
#include <cuda_runtime.h>
#include <cstdint>
#include <climits>

// VQ-VAE quantizer: exact-int8 dp4a candidate search + bit-exact fp32 refinement.
//
//  Stage A (dp4a): dot_int(t,k) = <a_t, b_k> exactly in int32, where a = rint(x/s_x),
//    b = rint(c/s_c). Per (token, column-of-64-codes): track top-2 values + argmax.
//  Stage B: sound margin M_t (worst-case quantization + sumc2-span + fp32 rounding
//    skew) selects columns/codes that could contain the true argmin; those are
//    re-scored with the exact fp32 pipeline that produced rel_err = 0.0 in round 4
//    (sequential-d fmaf dot; dist = fmaf(-2,dot,sx+sc2); u64-key first-index ties).

typedef unsigned long long u64;
typedef unsigned int u32;

#define D        64
#define NCODES   1024
#define BT       128
#define NBLOCKS  2048
#define SC_INV   130048.f          // 1/s_c = 1024*127
#define SC_VAL   (1.f/130048.f)

// ---- smem byte offsets ----
#define SM_CQ    0                 // u32[16][1024] quantized codes   65536
#define SM_XQ    65536             // u32[16][128]  quantized tokens   8192
#define SM_M1    73728             // i32[128][16] column max          8192
#define SM_M2    81920             // i32[128][16] column 2nd          8192
#define SM_I1    90112             // i32[128][16] column argmax       8192
#define SM_SC2   98304             // f32[1024]                        4096
#define SM_MS    102400            // i32[128] margins                  512
#define SM_BIDX  102912            // i32[128]                          512
#define SM_PART  103424            // u64[128]                         1024
#define SMEM_TOTAL 104448

__device__ u32   g_cq[16 * NCODES];   // packed int8 codes, [dim-group][code]
__device__ float g_sumc2[NCODES];
__device__ float g_sacmax;            // max_k sum|c_k|
__device__ float g_sc2span;           // max-min sumc2
__device__ u64   g_block_loss[NBLOCKS];

__device__ __forceinline__ u32 smem_u32(const void* p) {
    u32 a; asm("{ .reg .u64 t; cvta.to.shared.u64 t, %1; cvt.u32.u64 %0, t; }" : "=r"(a) : "l"(p));
    return a;
}
__device__ __forceinline__ void cp16(u32 saddr, const void* g) {
    asm volatile("{ .reg .u64 gp; cvta.to.global.u64 gp, %1;"
                 " cp.async.cg.shared.global [%0], [gp], 16; }"
                 :: "r"(saddr), "l"(g) : "memory");
}
#define CP_COMMIT() asm volatile("cp.async.commit_group;" ::: "memory")
#define CP_WAIT0()  asm volatile("cp.async.wait_group 0;" ::: "memory")

__device__ __forceinline__ int clamp127(int v) {
    return v > 127 ? 127 : (v < -127 ? -127 : v);
}
__device__ __forceinline__ u32 pack4(int a0, int a1, int a2, int a3) {
    return (u32)(a0 & 0xFF) | ((u32)(a1 & 0xFF) << 8) |
           ((u32)(a2 & 0xFF) << 16) | ((u32)(a3 & 0xFF) << 24);
}

// Exact re-score: arithmetic identical to the round-4 (rel_err = 0.0) kernel.
__device__ __forceinline__ u64 exact_key(const float* __restrict__ xr,
                                         const float* __restrict__ cb,
                                         const float* __restrict__ sc2s,
                                         float sx, int ci) {
    const float* cr = cb + (size_t)ci * D;
    float dot = 0.f;
#pragma unroll 16
    for (int d = 0; d < D; d++) dot = fmaf(xr[d], cr[d], dot);
    float dist = fmaf(-2.f, dot, sx + sc2s[ci]);
    return ((u64)__float_as_uint(dist) << 32) | (u32)ci;
}

// ---------------------------------------------------------------------------
// Prep: int8-quantize codebook into [dim-group][code] layout; exact sumc2;
// block-reduced SACmax and sumc2 span. One block of 1024 threads.
// ---------------------------------------------------------------------------
__global__ void prep_kernel(const float* __restrict__ cb) {
    __shared__ float red[NCODES];
    const int k = threadIdx.x;
    float s = 0.f, sa = 0.f;
#pragma unroll
    for (int g = 0; g < 16; g++) {
        float v0 = cb[(size_t)k * D + 4 * g + 0];
        float v1 = cb[(size_t)k * D + 4 * g + 1];
        float v2 = cb[(size_t)k * D + 4 * g + 2];
        float v3 = cb[(size_t)k * D + 4 * g + 3];
        s = fmaf(v0, v0, s); s = fmaf(v1, v1, s);
        s = fmaf(v2, v2, s); s = fmaf(v3, v3, s);
        sa += fabsf(v0) + fabsf(v1) + fabsf(v2) + fabsf(v3);
        g_cq[g * NCODES + k] = pack4(
            clamp127(__float2int_rn(v0 * SC_INV)),
            clamp127(__float2int_rn(v1 * SC_INV)),
            clamp127(__float2int_rn(v2 * SC_INV)),
            clamp127(__float2int_rn(v3 * SC_INV)));
    }
    g_sumc2[k] = s;

    // max sum|c|
    red[k] = sa; __syncthreads();
    for (int st = 512; st > 0; st >>= 1) {
        if (k < st) red[k] = fmaxf(red[k], red[k + st]);
        __syncthreads();
    }
    if (k == 0) g_sacmax = red[0];
    __syncthreads();
    // sumc2 span
    red[k] = s; __syncthreads();
    for (int st = 512; st > 0; st >>= 1) {
        if (k < st) red[k] = fmaxf(red[k], red[k + st]);
        __syncthreads();
    }
    float smax = red[0]; __syncthreads();
    red[k] = s; __syncthreads();
    for (int st = 512; st > 0; st >>= 1) {
        if (k < st) red[k] = fminf(red[k], red[k + st]);
        __syncthreads();
    }
    if (k == 0) g_sc2span = smax - red[0];
}

// ---------------------------------------------------------------------------
// Main kernel: 256 threads, 128 tokens/block. ty=tid>>4 owns 8 tokens,
// tx=tid&15 owns code column {ch*128 + tx*8 + j}. All 1024 codes in smem.
// ---------------------------------------------------------------------------
__global__ __launch_bounds__(256, 2)
void vq_kernel(const float* __restrict__ x,
               const float* __restrict__ cb,
               float* __restrict__ out_q,
               float* __restrict__ out_idx) {
    extern __shared__ char smem[];
    const u32 sb  = smem_u32(smem);
    const int tid = threadIdx.x;
    const int t0  = blockIdx.x * BT;

    u32*   cqp   = (u32*)(smem + SM_CQ);
    u32*   xqp   = (u32*)(smem + SM_XQ);
    int*   colm1 = (int*)(smem + SM_M1);
    int*   colm2 = (int*)(smem + SM_M2);
    int*   coli1 = (int*)(smem + SM_I1);
    float* sc2s  = (float*)(smem + SM_SC2);
    int*   Ms    = (int*)(smem + SM_MS);
    int*   bidx  = (int*)(smem + SM_BIDX);
    u64*   part  = (u64*)(smem + SM_PART);

    // Codes gmem->smem (64 KB, async)
    for (u32 off = tid * 16; off < 16 * NCODES * 4; off += 256 * 16)
        cp16(sb + SM_CQ + off, (const char*)g_cq + off);
    CP_COMMIT();

    for (int i = tid; i < NCODES; i += 256) sc2s[i] = g_sumc2[i];

    // Per-token quantization + sound margin (tid < 128)
    if (tid < BT) {
        const float* xr = x + (size_t)(t0 + tid) * D;
        float xmax = 0.f, s1 = 0.f;
#pragma unroll 16
        for (int d = 0; d < D; d++) {
            float a = fabsf(xr[d]);
            xmax = fmaxf(xmax, a);
            s1 += a;
        }
        xmax = fmaxf(xmax, 1e-30f);
        const float s_x = xmax / 127.f;
        const float inv = 127.f / xmax;
#pragma unroll
        for (int g = 0; g < 16; g++) {
            xqp[g * BT + tid] = pack4(
                clamp127(__float2int_rn(xr[4 * g + 0] * inv)),
                clamp127(__float2int_rn(xr[4 * g + 1] * inv)),
                clamp127(__float2int_rn(xr[4 * g + 2] * inv)),
                clamp127(__float2int_rn(xr[4 * g + 3] * inv)));
        }
        // Worst-case |dot_real - s_x*s_c*dot_int| bound + sumc2 span + fp32
        // rounding skew of the exact pipeline (token-common terms cancel).
        float err   = 0.5f * SC_VAL * s1 + 0.5f * s_x * g_sacmax + 16.f * s_x * SC_VAL;
        float Mreal = 2.f * err + 0.5f * g_sc2span + 1e-4f;
        Ms[tid] = (int)ceilf(Mreal / (s_x * SC_VAL) * 1.05f) + 64;
    }
    CP_WAIT0();
    __syncthreads();

    const int ty = tid >> 4, tx = tid & 15;

    int m1[8], m2[8], i1[8];
#pragma unroll
    for (int i = 0; i < 8; i++) { m1[i] = INT_MIN; m2[i] = INT_MIN; i1[i] = 0; }

    for (int ch = 0; ch < 8; ch++) {
        const int cb0 = ch * 128 + tx * 8;
        int acc[8][8];
#pragma unroll
        for (int i = 0; i < 8; i++)
#pragma unroll
            for (int j = 0; j < 8; j++) acc[i][j] = 0;

#pragma unroll
        for (int g = 0; g < 16; g++) {
            uint4 xa0 = *(uint4*)&xqp[g * BT + ty * 8];
            uint4 xa1 = *(uint4*)&xqp[g * BT + ty * 8 + 4];
            uint4 cv0 = *(uint4*)&cqp[g * NCODES + cb0];
            uint4 cv1 = *(uint4*)&cqp[g * NCODES + cb0 + 4];
            u32 xa[8] = {xa0.x, xa0.y, xa0.z, xa0.w, xa1.x, xa1.y, xa1.z, xa1.w};
            u32 cv[8] = {cv0.x, cv0.y, cv0.z, cv0.w, cv1.x, cv1.y, cv1.z, cv1.w};
#pragma unroll
            for (int i = 0; i < 8; i++)
#pragma unroll
                for (int j = 0; j < 8; j++)
                    acc[i][j] = __dp4a((int)xa[i], (int)cv[j], acc[i][j]);
        }

        // top-2 per token within this thread's column
#pragma unroll
        for (int i = 0; i < 8; i++)
#pragma unroll
            for (int j = 0; j < 8; j++) {
                int v = acc[i][j];
                if (v > m2[i]) {
                    if (v > m1[i]) { m2[i] = m1[i]; m1[i] = v; i1[i] = cb0 + j; }
                    else           { m2[i] = v; }
                }
            }
    }

#pragma unroll
    for (int i = 0; i < 8; i++) {
        const int t = ty * 8 + i;
        colm1[t * 16 + tx] = m1[i];
        colm2[t * 16 + tx] = m2[i];
        coli1[t * 16 + tx] = i1[i];
    }
    __syncthreads();

    // ---- Exact refinement (token = tid for tid < 128) ----
    if (tid < BT) {
        const int t = tid;
        int gmax = INT_MIN;
#pragma unroll
        for (int c = 0; c < 16; c++) gmax = max(gmax, colm1[t * 16 + c]);
        const int thr = gmax - Ms[t];

        const float* xr = x + (size_t)(t0 + t) * D;
        float sx = 0.f;
#pragma unroll 16
        for (int d = 0; d < D; d++) sx = fmaf(xr[d], xr[d], sx);

        u64 best = 0xFFFFFFFFFFFFFFFFull;
        for (int c = 0; c < 16; c++) {
            if (colm1[t * 16 + c] < thr) continue;
            if (colm2[t * 16 + c] >= thr) {
                // whole column could hide the argmin: exact rescan of its 64 codes
                for (int ch2 = 0; ch2 < 8; ch2++) {
#pragma unroll
                    for (int j = 0; j < 8; j++) {
                        u64 key = exact_key(xr, cb, sc2s, sx, ch2 * 128 + c * 8 + j);
                        if (key < best) best = key;
                    }
                }
            } else {
                u64 key = exact_key(xr, cb, sc2s, sx, coli1[t * 16 + c]);
                if (key < best) best = key;
            }
        }

        const int   besti = (int)(best & 0xFFFFFFFFull);
        const float bestd = __uint_as_float((u32)(best >> 32));
        bidx[t] = besti;
        out_idx[t0 + t] = (float)besti;
        part[t] = (u64)llrintf(bestd * 1073741824.f);   // Q30 fixed point
    }
    __syncthreads();

    if (tid == 0) {
        u64 s = 0;
        for (int k = 0; k < BT; k++) s += part[k];
        g_block_loss[blockIdx.x] = s;                   // fresh write: deterministic
    }

    // Quantized output, coalesced; straight-through rounding x + (q - x)
    for (int idx = tid; idx < BT * D; idx += 256) {
        int t = idx >> 6, d = idx & 63;
        float q  = __ldg(&cb[(size_t)bidx[t] * D + d]);
        float xv = x[(size_t)(t0 + t) * D + d];
        out_q[(size_t)(t0 + t) * D + d] = xv + (q - xv);
    }
}

// ---------------------------------------------------------------------------
// Finalize: loss = m + 0.25*m, m = mean(best_dist) over N*D elements
// ---------------------------------------------------------------------------
__global__ void finalize_kernel(float* __restrict__ out_loss, double inv_count) {
    __shared__ u64 sh[256];
    u64 s = 0;
    for (int i = threadIdx.x; i < NBLOCKS; i += 256) s += g_block_loss[i];
    sh[threadIdx.x] = s;
    __syncthreads();
    for (int st = 128; st > 0; st >>= 1) {
        if (threadIdx.x < st) sh[threadIdx.x] += sh[threadIdx.x + st];
        __syncthreads();
    }
    if (threadIdx.x == 0) {
        double tot = (double)sh[0] * (1.0 / 1073741824.0);
        float  m   = (float)(tot * inv_count);
        out_loss[0] = m + 0.25f * m;
    }
}

extern "C" void kernel_launch(void* const* d_in, const int* in_sizes, int n_in,
                              void* d_out, int out_size) {
    const float* x  = (const float*)d_in[0];
    const float* cb = (const float*)d_in[1];
    float* out = (float*)d_out;

    const int n = in_sizes[0] / D;            // 262144 tokens
    float* out_q    = out;
    float* out_loss = out + (size_t)n * D;
    float* out_idx  = out_loss + 1;

    cudaFuncSetAttribute(vq_kernel, cudaFuncAttributeMaxDynamicSharedMemorySize,
                         SMEM_TOTAL);

    prep_kernel<<<1, NCODES>>>(cb);
    vq_kernel<<<n / BT, 256, SMEM_TOTAL>>>(x, cb, out_q, out_idx);
    finalize_kernel<<<1, 256>>>(out_loss, 1.0 / ((double)n * D));
}

// round 8
// speedup vs baseline: 4.1817x; 4.1817x over previous
#include <cuda_runtime.h>
#include <cstdint>
#include <climits>

// VQ-VAE quantizer: exact-int8 dp4a scan + sound margin + bit-exact fp32 refinement.
//  dist_e(k) = sx + sc2_k - 2*dot_k  (reference-identical fp32 pipeline, rel_err=0.0)
//  scan value v_k = <qx, qc> exact int32; dist_e(k) = sx - 2*s_x*s_c*v_k + delta_k,
//  span(delta) <= sc2span + 4*e_q + rho  =>  select v_k >= vmax - M_int, rescore exactly.

typedef unsigned long long u64;
typedef unsigned int u32;

#define D        64
#define NCODES   1024
#define BT       128
#define NBLOCKS  2048
#define SC_INV   130048.f          // 1/s_c = 1024*127 (codes: |c| <= 1/1024)
#define SC_VAL   (1.f/130048.f)

// ---- smem byte offsets ----
#define SM_CQ    0                 // u32[16][1024] packed int8 codes   65536
#define SM_XQ    65536             // u32[16][128]  packed int8 tokens   8192
#define SM_M1    73728             // i32[128][16]                       8192
#define SM_M2    81920             // i32[128][16]                       8192
#define SM_I1    90112             // i32[128][16]                       8192
#define SM_SC2   98304             // f32[1024]                          4096
#define SM_MS    102400            // i32[128]                            512
#define SM_SX    102912            // f32[128]                            512
#define SM_BIDX  103424            // i32[128]                            512
#define SM_PART  103936            // u64[128]                           1024
#define SMEM_TOTAL 104960          // 102.5 KB -> 2 blocks/SM

__device__ u32   g_cq[16 * NCODES];   // packed int8 codes, [dim-group][code]
__device__ float g_sumc2[NCODES];
__device__ float g_sabs[NCODES];
__device__ float g_sacmax;            // max_k sum|c_k|
__device__ float g_sc2span;           // max-min sumc2
__device__ u64   g_block_loss[NBLOCKS];

__device__ __forceinline__ u32 smem_u32(const void* p) {
    u32 a; asm("{ .reg .u64 t; cvta.to.shared.u64 t, %1; cvt.u32.u64 %0, t; }" : "=r"(a) : "l"(p));
    return a;
}
__device__ __forceinline__ void cp16(u32 saddr, const void* g) {
    asm volatile("{ .reg .u64 gp; cvta.to.global.u64 gp, %1;"
                 " cp.async.cg.shared.global [%0], [gp], 16; }"
                 :: "r"(saddr), "l"(g) : "memory");
}
#define CP_COMMIT() asm volatile("cp.async.commit_group;" ::: "memory")
#define CP_WAIT0()  asm volatile("cp.async.wait_group 0;" ::: "memory")

__device__ __forceinline__ int clamp127(int v) {
    return v > 127 ? 127 : (v < -127 ? -127 : v);
}
__device__ __forceinline__ u32 pack4(int a0, int a1, int a2, int a3) {
    return (u32)(a0 & 0xFF) | ((u32)(a1 & 0xFF) << 8) |
           ((u32)(a2 & 0xFF) << 16) | ((u32)(a3 & 0xFF) << 24);
}

// Exact re-score: arithmetic identical to the round-4 (rel_err = 0.0) kernel.
__device__ __forceinline__ u64 exact_key(const float* __restrict__ xr,
                                         const float* __restrict__ cb,
                                         const float* __restrict__ sc2s,
                                         float sx, int ci) {
    const float* cr = cb + (size_t)ci * D;
    float dot = 0.f;
#pragma unroll 16
    for (int d = 0; d < D; d++) dot = fmaf(xr[d], cr[d], dot);
    float dist = fmaf(-2.f, dot, sx + sc2s[ci]);
    return ((u64)__float_as_uint(dist) << 32) | (u32)ci;
}

// ---------------------------------------------------------------------------
// Prep 1 (grid 8 x 128): quantize codebook, exact sumc2 (ref-order fma), sum|c|.
// ---------------------------------------------------------------------------
__global__ void prep_kernel(const float* __restrict__ cb) {
    const int k = blockIdx.x * 128 + threadIdx.x;
    float s = 0.f, sa = 0.f;
#pragma unroll
    for (int g = 0; g < 16; g++) {
        float v0 = cb[(size_t)k * D + 4 * g + 0];
        float v1 = cb[(size_t)k * D + 4 * g + 1];
        float v2 = cb[(size_t)k * D + 4 * g + 2];
        float v3 = cb[(size_t)k * D + 4 * g + 3];
        s = fmaf(v0, v0, s); s = fmaf(v1, v1, s);
        s = fmaf(v2, v2, s); s = fmaf(v3, v3, s);
        sa += fabsf(v0) + fabsf(v1) + fabsf(v2) + fabsf(v3);
        g_cq[g * NCODES + k] = pack4(
            clamp127(__float2int_rn(v0 * SC_INV)),
            clamp127(__float2int_rn(v1 * SC_INV)),
            clamp127(__float2int_rn(v2 * SC_INV)),
            clamp127(__float2int_rn(v3 * SC_INV)));
    }
    g_sumc2[k] = s;
    g_sabs[k]  = sa;
}

// ---------------------------------------------------------------------------
// Prep 2 (1 x 256): reductions for the sound margin.
// ---------------------------------------------------------------------------
__global__ void prep2_kernel() {
    __shared__ float ra[256], rb[256], rc[256];
    const int t = threadIdx.x;
    float ma = -1e30f, mb = -1e30f, mc = 1e30f;
    for (int i = t; i < NCODES; i += 256) {
        ma = fmaxf(ma, g_sabs[i]);
        float s = g_sumc2[i];
        mb = fmaxf(mb, s);
        mc = fminf(mc, s);
    }
    ra[t] = ma; rb[t] = mb; rc[t] = mc;
    __syncthreads();
    for (int st = 128; st > 0; st >>= 1) {
        if (t < st) {
            ra[t] = fmaxf(ra[t], ra[t + st]);
            rb[t] = fmaxf(rb[t], rb[t + st]);
            rc[t] = fminf(rc[t], rc[t + st]);
        }
        __syncthreads();
    }
    if (t == 0) { g_sacmax = ra[0]; g_sc2span = rb[0] - rc[0]; }
}

// ---------------------------------------------------------------------------
// Main kernel: 256 threads, 128 tokens/block; ty=tid>>4 owns 8 tokens,
// tx=tid&15 owns codes {ch*128 + tx*8 + j}. All codes int8 in smem.
// ---------------------------------------------------------------------------
__global__ __launch_bounds__(256, 2)
void vq_kernel(const float* __restrict__ x,
               const float* __restrict__ cb,
               float* __restrict__ out_q,
               float* __restrict__ out_idx) {
    extern __shared__ char smem[];
    const u32 sb  = smem_u32(smem);
    const int tid = threadIdx.x;
    const int t0  = blockIdx.x * BT;

    u32*   cqp   = (u32*)(smem + SM_CQ);
    u32*   xqp   = (u32*)(smem + SM_XQ);
    int*   colm1 = (int*)(smem + SM_M1);
    int*   colm2 = (int*)(smem + SM_M2);
    int*   coli1 = (int*)(smem + SM_I1);
    float* sc2s  = (float*)(smem + SM_SC2);
    int*   Ms    = (int*)(smem + SM_MS);
    float* sxs   = (float*)(smem + SM_SX);
    int*   bidx  = (int*)(smem + SM_BIDX);
    u64*   part  = (u64*)(smem + SM_PART);

    // Codes gmem->smem (64 KB, async; L2-resident after first wave)
    for (u32 off = tid * 16; off < 16 * NCODES * 4; off += 256 * 16)
        cp16(sb + SM_CQ + off, (const char*)g_cq + off);
    CP_COMMIT();

    for (int i = tid; i < NCODES; i += 256) sc2s[i] = g_sumc2[i];

    // Per-token prologue (tid < 128): stats + quantize + sound margin
    if (tid < BT) {
        const float* xr = x + (size_t)(t0 + tid) * D;
        float xmax = 1e-30f, s1 = 0.f, sx = 0.f;
#pragma unroll 16
        for (int d = 0; d < D; d++) {
            float v = xr[d];
            sx = fmaf(v, v, sx);              // reference-order sum(x^2)
            float a = fabsf(v);
            xmax = fmaxf(xmax, a);
            s1 += a;
        }
        sxs[tid] = sx;
        const float s_x = xmax / 127.f;
        const float inv = 127.f / xmax;
#pragma unroll
        for (int g = 0; g < 16; g++) {
            xqp[g * BT + tid] = pack4(
                clamp127(__float2int_rn(xr[4 * g + 0] * inv)),
                clamp127(__float2int_rn(xr[4 * g + 1] * inv)),
                clamp127(__float2int_rn(xr[4 * g + 2] * inv)),
                clamp127(__float2int_rn(xr[4 * g + 3] * inv)));
        }
        // e_q >= |dot - s_x*s_c*acc|; margin span = sc2span + 4*e_q + fp32 skew
        float e_q    = 0.5f * SC_VAL * s1 + 0.5f * s_x * g_sacmax
                     + 16.f * s_x * SC_VAL;
        float M_dist = g_sc2span + 4.f * e_q + 4e-5f;
        Ms[tid] = (int)ceilf(M_dist / (2.f * s_x * SC_VAL)) + 8;
    }
    CP_WAIT0();
    __syncthreads();

    const int ty = tid >> 4, tx = tid & 15;

    int m1[8], m2[8], i1[8];
#pragma unroll
    for (int i = 0; i < 8; i++) { m1[i] = INT_MIN; m2[i] = INT_MIN; i1[i] = 0; }

    for (int ch = 0; ch < 8; ch++) {
        const int cb0 = ch * 128 + tx * 8;
        int acc[8][8];
#pragma unroll
        for (int i = 0; i < 8; i++)
#pragma unroll
            for (int j = 0; j < 8; j++) acc[i][j] = 0;

#pragma unroll
        for (int g = 0; g < 16; g++) {
            uint4 xa0 = *(uint4*)&xqp[g * BT + ty * 8];
            uint4 xa1 = *(uint4*)&xqp[g * BT + ty * 8 + 4];
            uint4 cv0 = *(uint4*)&cqp[g * NCODES + cb0];
            uint4 cv1 = *(uint4*)&cqp[g * NCODES + cb0 + 4];
            u32 xa[8] = {xa0.x, xa0.y, xa0.z, xa0.w, xa1.x, xa1.y, xa1.z, xa1.w};
            u32 cv[8] = {cv0.x, cv0.y, cv0.z, cv0.w, cv1.x, cv1.y, cv1.z, cv1.w};
#pragma unroll
            for (int i = 0; i < 8; i++)
#pragma unroll
                for (int j = 0; j < 8; j++)
                    acc[i][j] = __dp4a((int)xa[i], (int)cv[j], acc[i][j]);
        }

#pragma unroll
        for (int i = 0; i < 8; i++)
#pragma unroll
            for (int j = 0; j < 8; j++) {
                int v = acc[i][j];
                if (v > m2[i]) {
                    if (v > m1[i]) { m2[i] = m1[i]; m1[i] = v; i1[i] = cb0 + j; }
                    else           { m2[i] = v; }
                }
            }
    }

#pragma unroll
    for (int i = 0; i < 8; i++) {
        const int t = ty * 8 + i;
        colm1[t * 16 + tx] = m1[i];
        colm2[t * 16 + tx] = m2[i];
        coli1[t * 16 + tx] = i1[i];
    }
    __syncthreads();

    // ---- Refinement (token = tid < 128): exact-rescore all codes >= thr ----
    if (tid < BT) {
        const int t = tid;
        int gmax = INT_MIN;
#pragma unroll
        for (int c = 0; c < 16; c++) gmax = max(gmax, colm1[t * 16 + c]);
        const int thr = gmax - Ms[t];

        const float* xr = x + (size_t)(t0 + t) * D;   // L1-hot from prologue
        const float  sx = sxs[t];

        u64 best = 0xFFFFFFFFFFFFFFFFull;
        for (int c = 0; c < 16; c++) {
            if (colm1[t * 16 + c] < thr) continue;
            u64 k1 = exact_key(xr, cb, sc2s, sx, coli1[t * 16 + c]);
            if (k1 < best) best = k1;
            if (colm2[t * 16 + c] >= thr) {
                // Rare: >=2 in-margin codes in this column. Cheap int rescan
                // from smem finds every code with acc >= thr (soundness: any
                // rank-3+ in-margin code implies m2 >= thr, so we land here).
                for (int ch2 = 0; ch2 < 8; ch2++) {
                    const int kb = ch2 * 128 + c * 8;
                    int aj[8];
#pragma unroll
                    for (int j = 0; j < 8; j++) aj[j] = 0;
#pragma unroll
                    for (int g = 0; g < 16; g++) {
                        const int xv = (int)xqp[g * BT + t];
#pragma unroll
                        for (int j = 0; j < 8; j++)
                            aj[j] = __dp4a(xv, (int)cqp[g * NCODES + kb + j], aj[j]);
                    }
#pragma unroll
                    for (int j = 0; j < 8; j++)
                        if (aj[j] >= thr) {
                            u64 k2 = exact_key(xr, cb, sc2s, sx, kb + j);
                            if (k2 < best) best = k2;
                        }
                }
            }
        }

        const int   besti = (int)(best & 0xFFFFFFFFull);
        const float bestd = __uint_as_float((u32)(best >> 32));
        bidx[t] = besti;
        out_idx[t0 + t] = (float)besti;
        part[t] = (u64)llrintf(bestd * 1073741824.f);   // Q30 fixed point
    }
    __syncthreads();

    if (tid == 0) {
        u64 s = 0;
        for (int k = 0; k < BT; k++) s += part[k];
        g_block_loss[blockIdx.x] = s;                   // fresh write: deterministic
    }

    // Quantized output, coalesced; straight-through rounding x + (q - x)
    for (int idx = tid; idx < BT * D; idx += 256) {
        int t = idx >> 6, d = idx & 63;
        float q  = __ldg(&cb[(size_t)bidx[t] * D + d]);
        float xv = x[(size_t)(t0 + t) * D + d];
        out_q[(size_t)(t0 + t) * D + d] = xv + (q - xv);
    }
}

// ---------------------------------------------------------------------------
// Finalize: loss = m + 0.25*m, m = mean(best_dist) over N*D elements
// ---------------------------------------------------------------------------
__global__ void finalize_kernel(float* __restrict__ out_loss, double inv_count) {
    __shared__ u64 sh[256];
    u64 s = 0;
    for (int i = threadIdx.x; i < NBLOCKS; i += 256) s += g_block_loss[i];
    sh[threadIdx.x] = s;
    __syncthreads();
    for (int st = 128; st > 0; st >>= 1) {
        if (threadIdx.x < st) sh[threadIdx.x] += sh[threadIdx.x + st];
        __syncthreads();
    }
    if (threadIdx.x == 0) {
        double tot = (double)sh[0] * (1.0 / 1073741824.0);
        float  m   = (float)(tot * inv_count);
        out_loss[0] = m + 0.25f * m;
    }
}

extern "C" void kernel_launch(void* const* d_in, const int* in_sizes, int n_in,
                              void* d_out, int out_size) {
    const float* x  = (const float*)d_in[0];
    const float* cb = (const float*)d_in[1];
    float* out = (float*)d_out;

    const int n = in_sizes[0] / D;            // 262144 tokens
    float* out_q    = out;
    float* out_loss = out + (size_t)n * D;
    float* out_idx  = out_loss + 1;

    cudaFuncSetAttribute(vq_kernel, cudaFuncAttributeMaxDynamicSharedMemorySize,
                         SMEM_TOTAL);

    prep_kernel<<<8, 128>>>(cb);
    prep2_kernel<<<1, 256>>>();
    vq_kernel<<<n / BT, 256, SMEM_TOTAL>>>(x, cb, out_q, out_idx);
    finalize_kernel<<<1, 256>>>(out_loss, 1.0 / ((double)n * D));
}